// round 3
// baseline (speedup 1.0000x reference)
#include <cuda_runtime.h>

#define NUM_SKILLS 300
#define EMB 256
#define CD 64
#define BB 512
#define SS 200

// Fused kernel: one block per batch row b.
// Phase A: pack q/r/valid into shared (threads 0..199); concurrently all 256
//          threads compute the collapsed einsum coefficients for e = t:
//            out[b,s,e] = qf*A[e] + att*B[e] + mast*C[e] + D[e]
// Phase B: O(S^2) triangular running counts -> per-row scalar float4 in shared.
// Phase C: store loop. Thread owns e4 = t&63 (one float4 of the E dim), keeps
//          its 4 coefficient float4s in REGISTERS, iterates rows t>>6, +4,...:
//          per 16B store = one broadcast LDS + one streaming STG.128.
__global__ void __launch_bounds__(256) fused_kernel(
    const int* __restrict__ q, const int* __restrict__ r,
    const float* __restrict__ skill_w, const float* __restrict__ skill_b,
    const float* __restrict__ att_w,   const float* __restrict__ att_b,
    const float* __restrict__ mast_w,  const float* __restrict__ mast_b,
    const float* __restrict__ proj_w,  const float* __restrict__ proj_b,
    float* __restrict__ out)
{
    __shared__ int    pack[SS];        // qc | valid<<9 | r<<10
    __shared__ float4 scal[SS];        // {qf, att, mast, valid}
    __shared__ float  shA[EMB], shB[EMB], shC[EMB], shD[EMB];

    const int blk = blockIdx.x;
    const int t   = threadIdx.x;

    // ---- Phase A1: pack row inputs into shared ----
    int qraw = 0;
    if (t < SS) {
        qraw = q[blk * SS + t];
        const int v  = (qraw >= 0) & (qraw < NUM_SKILLS);
        int qc = qraw < 0 ? 0 : (qraw > NUM_SKILLS - 1 ? NUM_SKILLS - 1 : qraw);
        const int rr = r[blk * SS + t] & 1;
        pack[t] = qc | (v << 9) | (rr << 10);
    }

    // ---- Phase A2: per-e coefficients (every thread, e = t) ----
    {
        const float* pw = proj_w + t * CD;
        float A = 0.f, Bv = 0.f, Cv = 0.f, D = proj_b[t];
        #pragma unroll
        for (int c = 0; c < 21; ++c) {
            const float p = pw[c];
            A = fmaf(skill_w[c], p, A);
            D = fmaf(skill_b[c], p, D);
        }
        #pragma unroll
        for (int c = 0; c < 21; ++c) {
            const float p = pw[21 + c];
            Bv = fmaf(att_w[c], p, Bv);
            D  = fmaf(att_b[c], p, D);
        }
        #pragma unroll
        for (int c = 0; c < 22; ++c) {
            const float p = pw[42 + c];
            Cv = fmaf(mast_w[c], p, Cv);
            D  = fmaf(mast_b[c], p, D);
        }
        shA[t] = A; shB[t] = Bv; shC[t] = Cv; shD[t] = D;
    }
    __syncthreads();

    // ---- Phase B: triangular running counts (threads 0..199) ----
    if (t < SS) {
        const int myq = pack[t] & 0x1FF;
        int att = 0, cor = 0;
        for (int tp = 0; tp <= t; ++tp) {
            const int w = pack[tp];                 // LDS broadcast
            const int m = (int)((w & 0x1FF) == myq) & (w >> 9);
            att += m & 1;
            cor += (m & (w >> 10)) & 1;
        }
        const float attf = (float)att;
        const float mast = (float)cor / fmaxf(attf, 1.0f);
        const int   vbit = (pack[t] >> 9) & 1;
        scal[t] = make_float4((float)qraw, attf, mast, vbit ? 1.0f : 0.0f);
    }
    __syncthreads();

    // ---- Phase C: store loop, coefficients in registers ----
    const int e4 = t & 63;
    const int rl = t >> 6;
    const float4 a = reinterpret_cast<const float4*>(shA)[e4];
    const float4 b = reinterpret_cast<const float4*>(shB)[e4];
    const float4 c = reinterpret_cast<const float4*>(shC)[e4];
    const float4 d = reinterpret_cast<const float4*>(shD)[e4];

    float4* __restrict__ out4 = reinterpret_cast<float4*>(out);
    const int base = (blk * SS) * (EMB / 4) + e4;   // float4 index

    #pragma unroll 5
    for (int row = rl; row < SS; row += 4) {
        const float4 s = scal[row];                 // LDS broadcast across 64 thr
        float4 o;
        if (s.w != 0.0f) {
            o.x = fmaf(s.x, a.x, fmaf(s.y, b.x, fmaf(s.z, c.x, d.x)));
            o.y = fmaf(s.x, a.y, fmaf(s.y, b.y, fmaf(s.z, c.y, d.y)));
            o.z = fmaf(s.x, a.z, fmaf(s.y, b.z, fmaf(s.z, c.z, d.z)));
            o.w = fmaf(s.x, a.w, fmaf(s.y, b.w, fmaf(s.z, c.w, d.w)));
        } else {
            o = make_float4(0.f, 0.f, 0.f, 0.f);
        }
        __stcs(&out4[base + row * (EMB / 4)], o);   // streaming store
    }
}

// Input order (metadata): 0=q 1=r 2=qry(unused) 3=skill_w 4=skill_b
// 5=att_w 6=att_b 7=mast_w 8=mast_b 9=proj_w 10=proj_b
extern "C" void kernel_launch(void* const* d_in, const int* in_sizes, int n_in,
                              void* d_out, int out_size)
{
    const int*   q       = (const int*)d_in[0];
    const int*   r       = (const int*)d_in[1];
    const float* skill_w = (const float*)d_in[3];
    const float* skill_b = (const float*)d_in[4];
    const float* att_w   = (const float*)d_in[5];
    const float* att_b   = (const float*)d_in[6];
    const float* mast_w  = (const float*)d_in[7];
    const float* mast_b  = (const float*)d_in[8];
    const float* proj_w  = (const float*)d_in[9];
    const float* proj_b  = (const float*)d_in[10];
    float* out = (float*)d_out;

    fused_kernel<<<BB, 256>>>(q, r, skill_w, skill_b, att_w, att_b,
                              mast_w, mast_b, proj_w, proj_b, out);
}

// round 4
// speedup vs baseline: 1.1354x; 1.1354x over previous
#include <cuda_runtime.h>

#define NUM_SKILLS 300
#define EMB 256
#define CD 64
#define BB 512
#define SS 200
#define ROWS_PER_BLOCK 32

// Global scratch (no allocations allowed).
__device__ float4 g_scal[BB * SS];   // {qf, attempts, mastery, valid}
__device__ float  g_A[EMB], g_B[EMB], g_C[EMB], g_D[EMB];

// ---------------------------------------------------------------------------
// Prep: blocks 0..511 -> per-row running counts (O(S^2) triangular, trivial).
// Block 512 -> collapsed einsum coefficients, warp-cooperative + coalesced:
//   out[b,s,e] = qf*A[e] + att*B[e] + mast*C[e] + D[e]
// ---------------------------------------------------------------------------
__global__ void __launch_bounds__(256) prep_kernel(
    const int* __restrict__ q, const int* __restrict__ r,
    const float* __restrict__ skill_w, const float* __restrict__ skill_b,
    const float* __restrict__ att_w,   const float* __restrict__ att_b,
    const float* __restrict__ mast_w,  const float* __restrict__ mast_b,
    const float* __restrict__ proj_w,  const float* __restrict__ proj_b)
{
    const int blk = blockIdx.x;
    const int t   = threadIdx.x;

    if (blk < BB) {
        __shared__ int pack[SS];   // qc | valid<<9 | r<<10
        int qraw = 0;
        if (t < SS) {
            qraw = q[blk * SS + t];
            const int v  = (qraw >= 0) & (qraw < NUM_SKILLS);
            int qc = qraw < 0 ? 0 : (qraw > NUM_SKILLS - 1 ? NUM_SKILLS - 1 : qraw);
            const int rr = r[blk * SS + t] & 1;
            pack[t] = qc | (v << 9) | (rr << 10);
        }
        __syncthreads();
        if (t < SS) {
            const int myq = pack[t] & 0x1FF;
            int att = 0, cor = 0;
            for (int tp = 0; tp <= t; ++tp) {
                const int w = pack[tp];
                const int m = (int)((w & 0x1FF) == myq) & ((w >> 9) & 1);
                att += m;
                cor += m & ((w >> 10) & 1);
            }
            const float attf = (float)att;
            const float mast = (float)cor / fmaxf(attf, 1.0f);
            const float vf   = ((pack[t] >> 9) & 1) ? 1.0f : 0.0f;
            g_scal[blk * SS + t] = make_float4((float)qraw, attf, mast, vf);
        }
    } else {
        // Coefficient block. wcat/bcat = concat of the three small vectors.
        __shared__ float wcat[CD], bcat[CD];
        if (t < 21)                    { wcat[t] = skill_w[t];      bcat[t] = skill_b[t]; }
        else if (t < 42)               { wcat[t] = att_w[t - 21];   bcat[t] = att_b[t - 21]; }
        else if (t < CD)               { wcat[t] = mast_w[t - 42];  bcat[t] = mast_b[t - 42]; }
        __syncthreads();

        const int w    = t >> 5;     // warp 0..7
        const int lane = t & 31;
        const float wlo = wcat[lane],      whi = wcat[lane + 32];
        const float blo = bcat[lane],      bhi = bcat[lane + 32];
        // segment routing: c<21 -> A, 21..41 -> B, 42..63 -> C
        const bool loA = lane < 21;                 // lo half (c = lane)
        const bool hiB = (lane + 32) < 42;          // hi half (c = lane+32)

        for (int e = w; e < EMB; e += 8) {
            const float p0 = proj_w[e * CD + lane];        // coalesced
            const float p1 = proj_w[e * CD + 32 + lane];   // coalesced
            float av = loA ? p0 * wlo : 0.0f;
            float bv = (loA ? 0.0f : p0 * wlo) + (hiB ? p1 * whi : 0.0f);
            float cv = hiB ? 0.0f : p1 * whi;
            float dv = fmaf(p0, blo, p1 * bhi);
            #pragma unroll
            for (int off = 16; off > 0; off >>= 1) {
                av += __shfl_xor_sync(0xFFFFFFFF, av, off);
                bv += __shfl_xor_sync(0xFFFFFFFF, bv, off);
                cv += __shfl_xor_sync(0xFFFFFFFF, cv, off);
                dv += __shfl_xor_sync(0xFFFFFFFF, dv, off);
            }
            if (lane == 0) {
                g_A[e] = av; g_B[e] = bv; g_C[e] = cv;
                g_D[e] = dv + proj_b[e];
            }
        }
    }
}

// ---------------------------------------------------------------------------
// Store kernel: 3200 blocks x 256 threads, 32 rows per block.
// Thread owns e4 = t&63 (one float4 of E) with its 4 coefficient float4s in
// REGISTERS, and iterates 8 rows (lane = t>>6; rows lane, lane+4, ...).
// Each warp has uniform lane -> uniform row -> scalar LDG is a broadcast;
// e4 spans 32 consecutive float4s -> stores fully coalesced (512B/warp).
// ---------------------------------------------------------------------------
__global__ void __launch_bounds__(256) out_kernel(float* __restrict__ out)
{
    const int e4   = threadIdx.x & 63;
    const int lane = threadIdx.x >> 6;          // 0..3
    const int bs0  = blockIdx.x * ROWS_PER_BLOCK;

    const float4 a = __ldg(&reinterpret_cast<const float4*>(g_A)[e4]);
    const float4 b = __ldg(&reinterpret_cast<const float4*>(g_B)[e4]);
    const float4 c = __ldg(&reinterpret_cast<const float4*>(g_C)[e4]);
    const float4 d = __ldg(&reinterpret_cast<const float4*>(g_D)[e4]);

    // Prefetch all 8 row scalars (independent LDGs -> MLP).
    float4 s[8];
    #pragma unroll
    for (int i = 0; i < 8; ++i)
        s[i] = __ldg(&g_scal[bs0 + lane + i * 4]);

    float4* __restrict__ out4 = reinterpret_cast<float4*>(out);

    #pragma unroll
    for (int i = 0; i < 8; ++i) {
        const int row = bs0 + lane + i * 4;
        float4 o;
        if (s[i].w != 0.0f) {
            o.x = fmaf(s[i].x, a.x, fmaf(s[i].y, b.x, fmaf(s[i].z, c.x, d.x)));
            o.y = fmaf(s[i].x, a.y, fmaf(s[i].y, b.y, fmaf(s[i].z, c.y, d.y)));
            o.z = fmaf(s[i].x, a.z, fmaf(s[i].y, b.z, fmaf(s[i].z, c.z, d.z)));
            o.w = fmaf(s[i].x, a.w, fmaf(s[i].y, b.w, fmaf(s[i].z, c.w, d.w)));
        } else {
            o = make_float4(0.f, 0.f, 0.f, 0.f);
        }
        out4[row * (EMB / 4) + e4] = o;
    }
}

// Input order (metadata): 0=q 1=r 2=qry(unused) 3=skill_w 4=skill_b
// 5=att_w 6=att_b 7=mast_w 8=mast_b 9=proj_w 10=proj_b
extern "C" void kernel_launch(void* const* d_in, const int* in_sizes, int n_in,
                              void* d_out, int out_size)
{
    const int*   q       = (const int*)d_in[0];
    const int*   r       = (const int*)d_in[1];
    const float* skill_w = (const float*)d_in[3];
    const float* skill_b = (const float*)d_in[4];
    const float* att_w   = (const float*)d_in[5];
    const float* att_b   = (const float*)d_in[6];
    const float* mast_w  = (const float*)d_in[7];
    const float* mast_b  = (const float*)d_in[8];
    const float* proj_w  = (const float*)d_in[9];
    const float* proj_b  = (const float*)d_in[10];
    float* out = (float*)d_out;

    prep_kernel<<<BB + 1, 256>>>(q, r, skill_w, skill_b, att_w, att_b,
                                 mast_w, mast_b, proj_w, proj_b);

    out_kernel<<<(BB * SS) / ROWS_PER_BLOCK, 256>>>(out);   // 3200 blocks
}

// round 6
// speedup vs baseline: 1.6948x; 1.4926x over previous
#include <cuda_runtime.h>

#define NUM_SKILLS 300
#define EMB 256
#define CD 64
#define BB 512
#define SS 200
#define RPB 20            // rows per block in main kernel
#define SEGS (SS / RPB)   // 10 segments per batch row

// Coefficient scratch (no allocations allowed).
// out[b,s,e] = qf*A[e] + att*B[e] + mast*C[e] + D[e]
__device__ float g_A[EMB], g_B[EMB], g_C[EMB], g_D[EMB];

// ---------------------------------------------------------------------------
// K1: coefficient kernel. 32 blocks x 256 threads = 256 warps, ONE warp per e.
// Lanes hold c = lane (lo) and c = lane+32 (hi) of proj_w row e (coalesced),
// route into A/B/C by segment (0..20 -> skill, 21..41 -> att, 42..63 -> mast),
// shuffle-reduce, lane 0 writes. Single shot -> no single-SM tail.
// ---------------------------------------------------------------------------
__global__ void __launch_bounds__(256) coef_kernel(
    const float* __restrict__ skill_w, const float* __restrict__ skill_b,
    const float* __restrict__ att_w,   const float* __restrict__ att_b,
    const float* __restrict__ mast_w,  const float* __restrict__ mast_b,
    const float* __restrict__ proj_w,  const float* __restrict__ proj_b)
{
    const int e    = blockIdx.x * 8 + (threadIdx.x >> 5);   // 0..255
    const int lane = threadIdx.x & 31;
    const int chi  = lane + 32;

    // per-lane weight/bias values (tiny arrays, L1-hot)
    const float wlo = (lane < 21) ? skill_w[lane] : att_w[lane - 21];
    const float blo = (lane < 21) ? skill_b[lane] : att_b[lane - 21];
    const float whi = (chi  < 42) ? att_w[chi - 21] : mast_w[chi - 42];
    const float bhi = (chi  < 42) ? att_b[chi - 21] : mast_b[chi - 42];

    const float p0 = proj_w[e * CD + lane];   // coalesced 128B
    const float p1 = proj_w[e * CD + chi];    // coalesced 128B

    const bool loA = lane < 21;
    const bool hiB = chi  < 42;

    float av = loA ? p0 * wlo : 0.0f;
    float bv = (loA ? 0.0f : p0 * wlo) + (hiB ? p1 * whi : 0.0f);
    float cv = hiB ? 0.0f : p1 * whi;
    float dv = fmaf(p0, blo, p1 * bhi);

    #pragma unroll
    for (int off = 16; off > 0; off >>= 1) {
        av += __shfl_xor_sync(0xFFFFFFFF, av, off);
        bv += __shfl_xor_sync(0xFFFFFFFF, bv, off);
        cv += __shfl_xor_sync(0xFFFFFFFF, cv, off);
        dv += __shfl_xor_sync(0xFFFFFFFF, dv, off);
    }
    if (lane == 0) {
        g_A[e] = av; g_B[e] = bv; g_C[e] = cv;
        g_D[e] = dv + proj_b[e];
    }
}

// ---------------------------------------------------------------------------
// K2: main kernel. 5120 blocks x 256 threads. Block = (batch b, 20-row segment).
// Phase 1: coalesced load of the row prefix pack[0..s0+19] into shared; all
//          threads concurrently fetch their 4 coefficient float4s (registers).
// Phase 2: threads 0..19 compute running counts for their row (LDS loop over
//          the prefix) -> scal[20] in shared. Redundancy factor 10 on a cheap
//          int loop; overlapped across resident blocks.
// Phase 3: store. Thread owns e4 = t&63, rows lane+4i (lane = t>>6, i<5):
//          per 16B output = 1 broadcast LDS + 3 FMA pairs + 1 STG.128.CS.
// ---------------------------------------------------------------------------
__global__ void __launch_bounds__(256) main_kernel(
    const int* __restrict__ q, const int* __restrict__ r,
    float* __restrict__ out)
{
    __shared__ int    pack[SS];     // qc | valid<<9 | r<<10
    __shared__ float4 scal[RPB];    // {qf, att, mast, valid}

    const int t   = threadIdx.x;
    const int b   = blockIdx.x / SEGS;
    const int s0  = (blockIdx.x % SEGS) * RPB;
    const int n   = s0 + RPB;       // prefix length needed

    // Phase 1a: prefix input loads first (they gate both barriers).
    int qraw = 0, rraw = 0;
    if (t < n) {
        qraw = q[b * SS + t];
        rraw = r[b * SS + t];
    }

    // Phase 1b: coefficient fetch (independent; overlaps with prefix loads).
    const int e4 = t & 63;
    const float4 a  = __ldg(&reinterpret_cast<const float4*>(g_A)[e4]);
    const float4 bc = __ldg(&reinterpret_cast<const float4*>(g_B)[e4]);
    const float4 cc = __ldg(&reinterpret_cast<const float4*>(g_C)[e4]);
    const float4 dc = __ldg(&reinterpret_cast<const float4*>(g_D)[e4]);

    if (t < n) {
        const int v  = (qraw >= 0) & (qraw < NUM_SKILLS);
        int qc = qraw < 0 ? 0 : (qraw > NUM_SKILLS - 1 ? NUM_SKILLS - 1 : qraw);
        pack[t] = qc | (v << 9) | ((rraw & 1) << 10);
    }
    __syncthreads();

    // Phase 2: counts for this block's 20 rows.
    if (t < RPB) {
        const int s   = s0 + t;
        const int w0  = pack[s];
        const int myq = w0 & 0x1FF;
        int att = 0, cor = 0;
        for (int tp = 0; tp <= s; ++tp) {
            const int w = pack[tp];
            const int m = (int)((w & 0x1FF) == myq) & ((w >> 9) & 1);
            att += m;
            cor += m & ((w >> 10) & 1);
        }
        const float attf = (float)att;
        const float mast = (float)cor / fmaxf(attf, 1.0f);
        const float vf   = ((w0 >> 9) & 1) ? 1.0f : 0.0f;
        // valid rows have qraw == qc (== myq); invalid rows are zeroed anyway
        scal[t] = make_float4((float)myq, attf, mast, vf);
    }
    __syncthreads();

    // Phase 3: store loop.
    const int lane = t >> 6;                         // 0..3
    float4* __restrict__ out4 = reinterpret_cast<float4*>(out);
    const int base = (b * SS + s0) * (EMB / 4) + e4; // float4 index of row s0

    #pragma unroll
    for (int i = 0; i < RPB / 4; ++i) {
        const int row = lane + i * 4;                // 0..19, uniform per warp
        const float4 s = scal[row];                  // LDS broadcast
        float4 o;
        if (s.w != 0.0f) {
            o.x = fmaf(s.x, a.x, fmaf(s.y, bc.x, fmaf(s.z, cc.x, dc.x)));
            o.y = fmaf(s.x, a.y, fmaf(s.y, bc.y, fmaf(s.z, cc.y, dc.y)));
            o.z = fmaf(s.x, a.z, fmaf(s.y, bc.z, fmaf(s.z, cc.z, dc.z)));
            o.w = fmaf(s.x, a.w, fmaf(s.y, bc.w, fmaf(s.z, cc.w, dc.w)));
        } else {
            o = make_float4(0.f, 0.f, 0.f, 0.f);
        }
        __stcs(&out4[base + row * (EMB / 4)], o);    // streaming store
    }
}

// Input order (metadata): 0=q 1=r 2=qry(unused) 3=skill_w 4=skill_b
// 5=att_w 6=att_b 7=mast_w 8=mast_b 9=proj_w 10=proj_b
extern "C" void kernel_launch(void* const* d_in, const int* in_sizes, int n_in,
                              void* d_out, int out_size)
{
    const int*   q       = (const int*)d_in[0];
    const int*   r       = (const int*)d_in[1];
    const float* skill_w = (const float*)d_in[3];
    const float* skill_b = (const float*)d_in[4];
    const float* att_w   = (const float*)d_in[5];
    const float* att_b   = (const float*)d_in[6];
    const float* mast_w  = (const float*)d_in[7];
    const float* mast_b  = (const float*)d_in[8];
    const float* proj_w  = (const float*)d_in[9];
    const float* proj_b  = (const float*)d_in[10];
    float* out = (float*)d_out;

    coef_kernel<<<EMB / 8, 256>>>(skill_w, skill_b, att_w, att_b,
                                  mast_w, mast_b, proj_w, proj_b);

    main_kernel<<<BB * SEGS, 256>>>(q, r, out);   // 5120 blocks
}